// round 11
// baseline (speedup 1.0000x reference)
#include <cuda_runtime.h>

// Shapes fixed by the problem: L=512, B=64, H=1024.
#define HDIM 1024
#define LDIM 512
#define BDIM 64
#define KSPLIT 64
#define KPER (HDIM / KSPLIT)   // 16
#define NCTA2 ((LDIM * BDIM) / 8)  // 4096 dot CTAs

// Scratch (device globals — no allocation allowed anywhere).
__device__ float g_wpart[KSPLIT * HDIM];
__device__ float g_w[HDIM];
__device__ float g_s[BDIM * LDIM];
__device__ unsigned int g_cnt1 = 0;   // self-resetting completion counters
__device__ unsigned int g_cnt2 = 0;

// ---------------------------------------------------------------------------
// K1: partial w + fused last-CTA reduce.
// grid (1, KSPLIT) x 256 threads; each thread owns 4 consecutive h (float4).
// 16 back-to-back LDG.128.CS per thread (W_att read exactly once).
// The LAST CTA to finish reduces g_wpart -> g_w (L2-resident, ~1-2us tail),
// eliminating the separate wreduce launch.
// ---------------------------------------------------------------------------
__global__ void __launch_bounds__(256) wpart_kernel(const float* __restrict__ W_att,
                                                    const float* __restrict__ vec) {
    const int h4 = threadIdx.x;                      // float4 index, 0..255
    const int kc = blockIdx.y;                       // k-chunk
    const float4* base =
        reinterpret_cast<const float4*>(W_att + (size_t)kc * KPER * (2 * HDIM) + HDIM) + h4;
    const float* vbase = vec + kc * KPER;
    float4 acc = make_float4(0.f, 0.f, 0.f, 0.f);
#pragma unroll
    for (int k = 0; k < KPER; ++k) {
        const float4 r = __ldcs(base + (size_t)k * (2 * HDIM / 4));
        const float  v = __ldg(vbase + k);
        acc.x += r.x * v; acc.y += r.y * v; acc.z += r.z * v; acc.w += r.w * v;
    }
    reinterpret_cast<float4*>(g_wpart + kc * HDIM)[h4] = acc;

    // ---- completion + last-CTA reduce ----
    __shared__ bool s_last;
    __syncthreads();
    if (threadIdx.x == 0) {
        __threadfence();
        const unsigned v = atomicAdd(&g_cnt1, 1);
        s_last = (v == KSPLIT - 1);
        if (s_last) g_cnt1 = 0;                      // reset for next graph replay
    }
    __syncthreads();
    if (!s_last) return;
    __threadfence();                                 // observe all CTAs' g_wpart

    float4 r = make_float4(0.f, 0.f, 0.f, 0.f);
#pragma unroll
    for (int j = 0; j < KSPLIT; ++j) {
        const float4 t = reinterpret_cast<const float4*>(g_wpart + j * HDIM)[h4];
        r.x += t.x; r.y += t.y; r.z += t.z; r.w += t.w;
    }
    reinterpret_cast<float4*>(g_w)[h4] = r;
}

// ---------------------------------------------------------------------------
// K2: the HBM-bound streaming dot (~128 MB read) + fused last-CTA softmax.
// One warp per (l,b) row: 8 back-to-back LDG.E.128.CS per lane (MLP=8),
// then w from smem inside the FMA loop. __launch_bounds__(256,4) pins
// <=64 regs so 4 CTAs (32 warps) co-reside per SM: 32KB in-flight per SM
// ~ 2x the latency-hiding need for ~8 TB/s at 577-cyc DRAM latency.
// Stores transposed g_s[b, l]; the LAST CTA then computes the softmax for
// all 64 b-rows from L2-resident g_s (8 warps x 8 rows), eliminating the
// 5.5us standalone softmax launch.
// grid 4096 x 256 threads.
// ---------------------------------------------------------------------------
__global__ void __launch_bounds__(256, 4) dot_kernel(const float* __restrict__ hs,
                                                     float* __restrict__ out) {
    __shared__ float4 ws4[HDIM / 4];
    const int tid = threadIdx.x;
    if (tid < HDIM / 4) ws4[tid] = reinterpret_cast<const float4*>(g_w)[tid];
    __syncthreads();

    const int warp = tid >> 5;
    const int lane = tid & 31;
    const int row  = blockIdx.x * 8 + warp;           // row = l*64 + b, 0..32767

    const float4* p = reinterpret_cast<const float4*>(hs + (size_t)row * HDIM);
    float4 a[8];
#pragma unroll
    for (int i = 0; i < 8; ++i) a[i] = __ldcs(p + lane + 32 * i);

    float acc = 0.f;
#pragma unroll
    for (int i = 0; i < 8; ++i) {
        const float4 w = ws4[lane + 32 * i];          // conflict-free LDS.128
        acc += a[i].x * w.x + a[i].y * w.y + a[i].z * w.z + a[i].w * w.w;
    }

#pragma unroll
    for (int off = 16; off; off >>= 1)
        acc += __shfl_xor_sync(0xffffffffu, acc, off);

    if (lane == 0) {
        const int l = row >> 6;     // / 64
        const int b = row & 63;     // % 64
        g_s[b * LDIM + l] = acc;
    }

    // ---- completion + last-CTA softmax ----
    __shared__ bool s_last;
    __syncthreads();
    if (tid == 0) {
        __threadfence();
        const unsigned v = atomicAdd(&g_cnt2, 1);
        s_last = (v == NCTA2 - 1);
        if (s_last) g_cnt2 = 0;                      // reset for next graph replay
    }
    __syncthreads();
    if (!s_last) return;
    __threadfence();                                 // observe all CTAs' g_s

    // 8 warps, each handles rows b = warp, warp+8, ... (8 rows each).
    const float4* s4 = reinterpret_cast<const float4*>(g_s);
    float4* o4 = reinterpret_cast<float4*>(out);
    for (int b = warp; b < BDIM; b += 8) {
        float4 v[4];
#pragma unroll
        for (int i = 0; i < 4; ++i) v[i] = s4[b * (LDIM / 4) + lane + 32 * i];

        float m = v[0].x;
#pragma unroll
        for (int i = 0; i < 4; ++i) {
            m = fmaxf(m, v[i].x); m = fmaxf(m, v[i].y);
            m = fmaxf(m, v[i].z); m = fmaxf(m, v[i].w);
        }
#pragma unroll
        for (int off = 16; off; off >>= 1)
            m = fmaxf(m, __shfl_xor_sync(0xffffffffu, m, off));

        float s = 0.f;
        float4 e[4];
#pragma unroll
        for (int i = 0; i < 4; ++i) {
            e[i].x = expf(v[i].x - m); e[i].y = expf(v[i].y - m);
            e[i].z = expf(v[i].z - m); e[i].w = expf(v[i].w - m);
            s += e[i].x + e[i].y + e[i].z + e[i].w;
        }
#pragma unroll
        for (int off = 16; off; off >>= 1)
            s += __shfl_xor_sync(0xffffffffu, s, off);

        const float inv = 1.f / s;
#pragma unroll
        for (int i = 0; i < 4; ++i) {
            o4[b * (LDIM / 4) + lane + 32 * i] =
                make_float4(e[i].x * inv, e[i].y * inv, e[i].z * inv, e[i].w * inv);
        }
    }
}

// ---------------------------------------------------------------------------
// Launch. Expected metadata order: hidden(0), hs_encoder(1), W_att(2),
// b_att(3), vector(4). hidden / Wh / b_att cancel under softmax
// shift-invariance (per-b constant added to every logit along l).
// hs_encoder and W_att are resolved by their unique element counts;
// vector = LAST input with H elements (b_att precedes vector in the dict).
// ---------------------------------------------------------------------------
extern "C" void kernel_launch(void* const* d_in, const int* in_sizes, int n_in,
                              void* d_out, int out_size) {
    const float* hs  = (const float*)d_in[1];
    const float* W   = (const float*)d_in[2];
    const float* vec = (const float*)d_in[4];
    for (int i = 0; i < n_in; ++i) {
        if (in_sizes[i] == LDIM * BDIM * HDIM) hs = (const float*)d_in[i];
        else if (in_sizes[i] == HDIM * 2 * HDIM) W = (const float*)d_in[i];
        else if (in_sizes[i] == HDIM) vec = (const float*)d_in[i];  // last H-sized wins
    }
    float* out = (float*)d_out;

    wpart_kernel<<<dim3(1, KSPLIT), 256>>>(W, vec);
    dot_kernel<<<NCTA2, 256>>>(hs, out);
}